// round 6
// baseline (speedup 1.0000x reference)
#include <cuda_runtime.h>
#include <cuda_bf16.h>
#include <cstdint>

#define BB 32
#define CC 80
#define HH 128
#define WW 128
#define HWSZ (HH * WW)      // 16384
#define KK 100
#define CAP 32768           // candidate slots per batch
#define NBINS 1024
#define BUFCAP 2560         // expected survivors/plane ~1820; overflow path correct

// Static device scratch (allocation-free per harness rules)
__device__ unsigned int g_cnt[BB];       // candidate counts (reset by stage2 path)
__device__ unsigned int g_done[BB];      // per-batch completion tickets
__device__ uint2 g_cand[BB * CAP];       // 8 MB candidate buffer

struct S1 { int hist[NBINS]; uint2 sbuf[BUFCAP]; };                       // 24.5 KB
struct S2 { int whist[8][256]; int hist2[256]; unsigned long long keys[1024]; }; // 17 KB
union SU { S1 a; S2 b; };

// ---------------------------------------------------------------------------
// Load one row (float4 per lane), compute horizontal 3-max per component.
__device__ __forceinline__ void ldrow(const float4* __restrict__ fp4, int y, int cg,
                                      float4& f4, float4& hm) {
    const float NEG = -1e30f;
    f4 = fp4[y * 32 + cg];
    float left  = __shfl_up_sync(0xffffffffu, f4.w, 1);
    float right = __shfl_down_sync(0xffffffffu, f4.x, 1);
    if (cg == 0)  left  = NEG;
    if (cg == 31) right = NEG;
    hm.x = fmaxf(fmaxf(left, f4.x), f4.y);
    hm.y = fmaxf(fmaxf(f4.x, f4.y), f4.z);
    hm.z = fmaxf(fmaxf(f4.y, f4.z), f4.w);
    hm.w = fmaxf(fmaxf(f4.z, f4.w), right);
}

__device__ __forceinline__ int val_bin(float v) {
    int bin = (int)(v * (float)NBINS);
    return max(0, min(NBINS - 1, bin));
}

// ---------------------------------------------------------------------------
__global__ __launch_bounds__(512) void k_fused(const float* __restrict__ fmap,
                                               const float* __restrict__ wh,
                                               const float* __restrict__ reg,
                                               float* __restrict__ out) {
    __shared__ SU sm;
    __shared__ int s_n, s_tbin, s_tk;
    __shared__ int s_byte, s_above, s_bucket, s_wcnt;

    const int plane = blockIdx.x;
    const int b = plane / CC;
    const int c = plane % CC;
    const float4* __restrict__ fp4 = (const float4*)(fmap + (size_t)plane * HWSZ);

    const int t = threadIdx.x;
    const int lane = t & 31;
    const unsigned lmlt = (1u << lane) - 1u;

    for (int i = t; i < NBINS; i += 512) sm.a.hist[i] = 0;
    if (t == 0) { s_n = 0; s_tbin = 0; }
    __syncthreads();

    // ---------------- stage 1: NMS + candidate staging -----------------
    const int cg = t & 31;
    const int y0 = (t >> 5) * 8;
    const float NEG = -1e30f;

    float4 fcur, fnext;
    float4 hA, hB, hC;
    if (y0 == 0) {
        hA = make_float4(NEG, NEG, NEG, NEG);
    } else {
        float4 d; ldrow(fp4, y0 - 1, cg, d, hA);
    }
    ldrow(fp4, y0, cg, fcur, hB);
    ldrow(fp4, y0 + 1, cg, fnext, hC);

#pragma unroll
    for (int r = 0; r < 8; r++) {
        const int y = y0 + r;
        float4 fnn, hD;
        if (r < 7) {
            if (y + 2 <= HH - 1) { ldrow(fp4, y + 2, cg, fnn, hD); }
            else { hD = make_float4(NEG, NEG, NEG, NEG); fnn = fnext; }
        }
        float4 vm;
        vm.x = fmaxf(fmaxf(hA.x, hB.x), hC.x);
        vm.y = fmaxf(fmaxf(hA.y, hB.y), hC.y);
        vm.z = fmaxf(fmaxf(hA.z, hB.z), hC.z);
        vm.w = fmaxf(fmaxf(hA.w, hB.w), hC.w);

        const float va[4] = {fcur.x, fcur.y, fcur.z, fcur.w};
        const float vb[4] = {vm.x, vm.y, vm.z, vm.w};
#pragma unroll
        for (int q = 0; q < 4; q++) {
            bool is = (va[q] >= vb[q]);               // 3x3 local maximum
            if (is) atomicAdd(&sm.a.hist[val_bin(va[q])], 1);
            unsigned bal = __ballot_sync(0xffffffffu, is);
            if (bal) {
                int cnt = __popc(bal);
                int leader = __ffs(bal) - 1;
                int base = 0;
                if (lane == leader) base = atomicAdd(&s_n, cnt);
                base = __shfl_sync(0xffffffffu, base, leader);
                if (is) {
                    int idx = base + __popc(bal & lmlt);
                    uint2 e = make_uint2(__float_as_uint(va[q]),
                                         (unsigned)c * HWSZ + (unsigned)(y * WW + cg * 4 + q));
                    if (idx < BUFCAP) sm.a.sbuf[idx] = e;
                    else {                             // overflow: direct append
                        unsigned g = atomicAdd(&g_cnt[b], 1u);
                        if (g < CAP) g_cand[(size_t)b * CAP + g] = e;
                    }
                }
            }
        }
        hA = hB; hB = hC;
        if (r < 7) { hC = hD; fcur = fnext; fnext = fnn; }
    }
    __syncthreads();

    // Warp 0: suffix-scan 1024 bins -> threshold bin keeping >= min(K, total)
    if (t < 32) {
        const int base = t * 32;
        int s = 0;
#pragma unroll
        for (int j = 0; j < 32; j++) s += sm.a.hist[base + j];
        int suf = s;
#pragma unroll
        for (int off = 1; off < 32; off <<= 1) {
            int v = __shfl_down_sync(0xffffffffu, suf, off);
            if (t + off < 32) suf += v;
        }
        const int total = __shfl_sync(0xffffffffu, suf, 0);
        const int need = min(KK, total);
        int sufN = __shfl_down_sync(0xffffffffu, suf, 1);
        if (t == 31) sufN = 0;
        if (need > 0 && suf >= need && sufN < need) {
            int acc = sufN, tb = base;
            for (int j = 31; j >= 0; j--) {
                acc += sm.a.hist[base + j];
                if (acc >= need) { tb = base + j; break; }
            }
            s_tbin = tb;
        }
    }
    __syncthreads();

    // Filter staged candidates, warp-aggregated append to g_cand[b]
    {
        const int tbin = s_tbin;
        const int n = min(s_n, BUFCAP);
        const int iters = (n + 511) / 512;
        for (int it = 0; it < iters; it++) {
            int i = t + it * 512;
            bool keep = false; uint2 cv;
            if (i < n) { cv = sm.a.sbuf[i]; keep = (val_bin(__uint_as_float(cv.x)) >= tbin); }
            unsigned bal = __ballot_sync(0xffffffffu, keep);
            if (bal) {
                int cnt = __popc(bal);
                int leader = __ffs(bal) - 1;
                unsigned base = 0;
                if (lane == leader) base = atomicAdd(&g_cnt[b], (unsigned)cnt);
                base = __shfl_sync(0xffffffffu, base, leader);
                if (keep) {
                    unsigned g = base + __popc(bal & lmlt);
                    if (g < CAP) g_cand[(size_t)b * CAP + g] = cv;
                }
            }
        }
    }

    // ---------------- completion ticket ----------------
    __threadfence();
    __syncthreads();
    if (t == 0) s_tk = (int)atomicAdd(&g_done[b], 1u);
    __syncthreads();
    if (s_tk != CC - 1) return;

    // ---------------- stage 2 (last block of batch b) ----------------
    __threadfence();   // acquire: make other blocks' g_cand writes visible
    __syncthreads();   // smem reuse boundary (sm.a -> sm.b)

    const int M = min((int)g_cnt[b], CAP);
    const uint2* __restrict__ cand = g_cand + (size_t)b * CAP;
    const int w = t >> 6;   // 8 sub-histograms

    unsigned T = 0u;
    {
        unsigned prefix = 0u, prefmask = 0u;
        int k = KK;
        int cnt_ge = M;
        for (int p = 3; p >= 0 && cnt_ge > 1024; p--) {
            for (int i = t; i < 8 * 256; i += 512) ((int*)sm.b.whist)[i] = 0;
            __syncthreads();
            const int sh = p * 8;
            for (int i = t; i < M; i += 512) {
                unsigned v = cand[i].x;
                if ((v & prefmask) == prefix)
                    atomicAdd(&sm.b.whist[w][(v >> sh) & 255], 1);
            }
            __syncthreads();
            if (t < 256) {
                int s = 0;
#pragma unroll
                for (int j = 0; j < 8; j++) s += sm.b.whist[j][t];
                sm.b.hist2[t] = s;
            }
            __syncthreads();
            if (t < 32) {     // warp0: suffix-scan 256 bins, find crossing
                const int base = t * 8;
                int s = 0;
#pragma unroll
                for (int j = 0; j < 8; j++) s += sm.b.hist2[base + j];
                int suf = s;
#pragma unroll
                for (int off = 1; off < 32; off <<= 1) {
                    int v = __shfl_down_sync(0xffffffffu, suf, off);
                    if (t + off < 32) suf += v;
                }
                int sufN = __shfl_down_sync(0xffffffffu, suf, 1);
                if (t == 31) sufN = 0;
                if (suf >= k && sufN < k) {
                    int acc = sufN;
                    for (int j = 7; j >= 0; j--) {
                        acc += sm.b.hist2[base + j];
                        if (acc >= k) {
                            s_byte = base + j;
                            s_above = acc - sm.b.hist2[base + j];
                            s_bucket = sm.b.hist2[base + j];
                            break;
                        }
                    }
                }
            }
            __syncthreads();
            prefix |= ((unsigned)s_byte) << sh;
            prefmask |= 0xFFu << sh;
            k -= s_above;
            cnt_ge = (KK - k) + s_bucket;
            __syncthreads();
        }
        T = prefix;    // {v >= T} has exactly cnt_ge members (<= 1024 normally)
    }

    if (t == 0) s_wcnt = 0;
    __syncthreads();
    for (int i = t; i < M; i += 512) {
        uint2 cv = cand[i];
        if (cv.x >= T) {
            int s = atomicAdd(&s_wcnt, 1);
            if (s < 1024)
                sm.b.keys[s] = ((unsigned long long)cv.x << 32) |
                               (unsigned long long)(0xFFFFFFFFu - cv.y);
        }
    }
    __syncthreads();
    const int n = min(s_wcnt, 1024);

    // Rank-based exact top-K: unique 64-bit keys -> unique ranks
    unsigned long long my0 = 0ull, my1 = 0ull;
    int r0 = 0, r1 = 0;
    const bool h0 = (t < n), h1 = (t + 512 < n);
    if (h0) my0 = sm.b.keys[t];
    if (h1) my1 = sm.b.keys[t + 512];
    for (int j = 0; j < n; j++) {
        unsigned long long kj = sm.b.keys[j];   // broadcast read
        r0 += (kj > my0);
        r1 += (kj > my1);
    }

    const float* __restrict__ whb = wh + (size_t)b * 2 * HWSZ;
    const float* __restrict__ regb = reg + (size_t)b * 2 * HWSZ;
#pragma unroll
    for (int e = 0; e < 2; e++) {
        bool have = e ? h1 : h0;
        int rk = e ? r1 : r0;
        unsigned long long key = e ? my1 : my0;
        if (have && rk < KK) {
            float val = __uint_as_float((unsigned)(key >> 32));
            unsigned pidx = 0xFFFFFFFFu - (unsigned)(key & 0xFFFFFFFFull);
            int cls = (int)(pidx >> 14);
            int pos = (int)(pidx & (HWSZ - 1));
            float yy = (float)(pos >> 7);
            float xx = (float)(pos & (WW - 1));
            float rx = regb[pos];
            float ry = regb[HWSZ + pos];
            float bw = whb[pos];
            float bh = whb[HWSZ + pos];
            float fx = xx + rx, fy = yy + ry;
            float hw2 = bw * 0.5f, hh2 = bh * 0.5f;
            float* bo = out + (size_t)(b * KK + rk) * 4;
            bo[0] = fx - hw2;
            bo[1] = fy - hh2;
            bo[2] = fx + hw2;
            bo[3] = fy + hh2;
            out[BB * KK * 4 + b * KK + rk] = val;                  // scores
            out[BB * KK * 4 + BB * KK + b * KK + rk] = (float)cls; // classes
        }
    }

    __syncthreads();
    if (t == 0) { g_cnt[b] = 0u; g_done[b] = 0u; }   // reset for next replay
}

// ---------------------------------------------------------------------------
extern "C" void kernel_launch(void* const* d_in, const int* in_sizes, int n_in,
                              void* d_out, int out_size) {
    const float* fmap = (const float*)d_in[0];
    const float* wh   = (const float*)d_in[1];
    const float* reg  = (const float*)d_in[2];
    float* out = (float*)d_out;

    k_fused<<<BB * CC, 512>>>(fmap, wh, reg, out);
}